// round 14
// baseline (speedup 1.0000x reference)
#include <cuda_runtime.h>
#include <cuda_bf16.h>
#include <cuda_fp16.h>
#include <math.h>
#include <stdint.h>

#define Bb 4
#define Ss 1024
#define Dd 1024
#define Hh 16
#define DKk 64

#define QSCALE 0.18033688011112042f
#define MASKVAL -14426.950408889634f

// ---------------------------------------------------------------------------
// Device scratch
// ---------------------------------------------------------------------------
__device__ __nv_bfloat16 g_Xb[2][4096 * 1024];   // bf16 q,k inputs
__device__ __half        g_Xf[4096 * 1024];      // fp16 v input
__device__ __nv_bfloat16 g_Wcb[2][1024 * 1024];  // folded Wq,Wk (bf16)
__device__ __half        g_Wcf[1024 * 1024];     // folded Wv (fp16)
__device__ float         g_bc[3][1024];          // folded biases
__device__ __nv_bfloat16 g_Qb[64 * 1024 * 64];   // per-head Q (bf16, pre-scaled)
__device__ __nv_bfloat16 g_Kb[64 * 1024 * 64];   // per-head K (bf16)
__device__ __half        g_Vp[64 * 1024 * 64];   // V' = V @ Wo^T (fp16) [bh][s][d]

// ---------------------------------------------------------------------------
// helpers
// ---------------------------------------------------------------------------
__device__ __forceinline__ void mma16(float (&d)[4], const uint32_t (&a)[4],
                                      uint32_t b0, uint32_t b1) {
    asm volatile(
        "mma.sync.aligned.m16n8k16.row.col.f32.bf16.bf16.f32 "
        "{%0,%1,%2,%3},{%4,%5,%6,%7},{%8,%9},{%0,%1,%2,%3};"
        : "+f"(d[0]), "+f"(d[1]), "+f"(d[2]), "+f"(d[3])
        : "r"(a[0]), "r"(a[1]), "r"(a[2]), "r"(a[3]), "r"(b0), "r"(b1));
}
__device__ __forceinline__ void mma16f(float (&d)[4], const uint32_t (&a)[4],
                                       uint32_t b0, uint32_t b1) {
    asm volatile(
        "mma.sync.aligned.m16n8k16.row.col.f32.f16.f16.f32 "
        "{%0,%1,%2,%3},{%4,%5,%6,%7},{%8,%9},{%0,%1,%2,%3};"
        : "+f"(d[0]), "+f"(d[1]), "+f"(d[2]), "+f"(d[3])
        : "r"(a[0]), "r"(a[1]), "r"(a[2]), "r"(a[3]), "r"(b0), "r"(b1));
}
__device__ __forceinline__ void ldsm4(uint32_t (&r)[4], const uint16_t* p) {
    uint32_t a = (uint32_t)__cvta_generic_to_shared(p);
    asm volatile("ldmatrix.sync.aligned.m8n8.x4.shared.b16 {%0,%1,%2,%3},[%4];"
                 : "=r"(r[0]), "=r"(r[1]), "=r"(r[2]), "=r"(r[3]) : "r"(a));
}
__device__ __forceinline__ void ldsm4t(uint32_t (&r)[4], const uint16_t* p) {
    uint32_t a = (uint32_t)__cvta_generic_to_shared(p);
    asm volatile("ldmatrix.sync.aligned.m8n8.x4.trans.shared.b16 {%0,%1,%2,%3},[%4];"
                 : "=r"(r[0]), "=r"(r[1]), "=r"(r[2]), "=r"(r[3]) : "r"(a));
}
__device__ __forceinline__ void cp16(void* s, const void* g) {
    uint32_t sa = (uint32_t)__cvta_generic_to_shared(s);
    asm volatile("cp.async.cg.shared.global [%0], [%1], 16;" :: "r"(sa), "l"(g));
}
__device__ __forceinline__ uint32_t pack_bf2(float a, float b) {
    __nv_bfloat162 t = __float22bfloat162_rn(make_float2(a, b));
    return *reinterpret_cast<uint32_t*>(&t);
}
__device__ __forceinline__ uint32_t pack_hf2(float a, float b) {
    __half2 t = __floats2half2_rn(a, b);
    return *reinterpret_cast<uint32_t*>(&t);
}
__device__ __forceinline__ float ex2f(float x) {
    float y; asm("ex2.approx.f32 %0,%1;" : "=f"(y) : "f"(x)); return y;
}

// ---------------------------------------------------------------------------
// Merged prologue:
//   blocks [0, 768)     : fold (vectorized LDS: Wf stored transposed)
//   blocks [768, 2816)  : preround
//   blocks [2816, 2819) : bfold
// ---------------------------------------------------------------------------
__global__ __launch_bounds__(256) void prologue(
    const float* __restrict__ q, const float* __restrict__ k, const float* __restrict__ v,
    const float* __restrict__ Wq, const float* __restrict__ Wqf,
    const float* __restrict__ Wk, const float* __restrict__ Wkf,
    const float* __restrict__ Wv, const float* __restrict__ Wvf,
    const float* __restrict__ bq, const float* __restrict__ bqf,
    const float* __restrict__ bk, const float* __restrict__ bkf,
    const float* __restrict__ bv, const float* __restrict__ bvf) {
    int bid = blockIdx.x;
    int tid = threadIdx.x;

    if (bid < 768) {
        // ---- fold: Wc[(h*64+o)*1024+j] = sum_i Wf[o,i] * Wbig[h*64+i, j] -----
        int t = bid >> 8, h = (bid >> 4) & 15, j0 = (bid & 15) * 64;
        const float* Wbig = (t == 0) ? Wq : (t == 1) ? Wk : Wv;
        const float* Wf   = (t == 0) ? Wqf : (t == 1) ? Wkf : Wvf;

        __shared__ float fsT[64][68];  // Wf transposed: fsT[i][o]
        __shared__ float bs[64][68];   // Wbig rows (pitch 68 -> 16B-aligned rows)

        for (int idx = tid; idx < 64 * 16; idx += 256) {
            int r = idx >> 4, c4 = (idx & 15) * 4;
            float4 fv = *(const float4*)(Wf + r * 64 + c4);
            fsT[c4][r] = fv.x; fsT[c4 + 1][r] = fv.y;
            fsT[c4 + 2][r] = fv.z; fsT[c4 + 3][r] = fv.w;
            float4 bv2 = *(const float4*)(Wbig + (h * 64 + r) * Dd + j0 + c4);
            *(float4*)&bs[r][c4] = bv2;
        }
        __syncthreads();

        int ty = tid >> 4, tx = tid & 15;
        float acc[4][4] = {};
#pragma unroll 8
        for (int i = 0; i < 64; i++) {
            float4 av = *(const float4*)&fsT[i][ty * 4];
            float4 bv2 = *(const float4*)&bs[i][tx * 4];
            float a[4] = {av.x, av.y, av.z, av.w};
            float b[4] = {bv2.x, bv2.y, bv2.z, bv2.w};
#pragma unroll
            for (int u = 0; u < 4; u++)
#pragma unroll
                for (int w = 0; w < 4; w++) acc[u][w] += a[u] * b[w];
        }
        if (t < 2) {
            uint32_t* dst = (uint32_t*)g_Wcb[t];
#pragma unroll
            for (int u = 0; u < 4; u++) {
                size_t row = (size_t)(h * 64 + ty * 4 + u) * Dd + j0 + tx * 4;
                dst[row / 2]     = pack_bf2(acc[u][0], acc[u][1]);
                dst[row / 2 + 1] = pack_bf2(acc[u][2], acc[u][3]);
            }
        } else {
            uint32_t* dst = (uint32_t*)g_Wcf;
#pragma unroll
            for (int u = 0; u < 4; u++) {
                size_t row = (size_t)(h * 64 + ty * 4 + u) * Dd + j0 + tx * 4;
                dst[row / 2]     = pack_hf2(acc[u][0], acc[u][1]);
                dst[row / 2 + 1] = pack_hf2(acc[u][2], acc[u][3]);
            }
        }
        return;
    }
    if (bid < 2816) {
        // ---- preround: 2 consecutive float4 per tensor per thread ------------
        size_t i = ((size_t)(bid - 768) * 256 + tid) * 2;
        {
            float4 a0 = ((const float4*)q)[i], a1 = ((const float4*)q)[i + 1];
            uint4 o = {pack_bf2(a0.x, a0.y), pack_bf2(a0.z, a0.w),
                       pack_bf2(a1.x, a1.y), pack_bf2(a1.z, a1.w)};
            ((uint4*)g_Xb[0])[i / 2] = o;
        }
        {
            float4 a0 = ((const float4*)k)[i], a1 = ((const float4*)k)[i + 1];
            uint4 o = {pack_bf2(a0.x, a0.y), pack_bf2(a0.z, a0.w),
                       pack_bf2(a1.x, a1.y), pack_bf2(a1.z, a1.w)};
            ((uint4*)g_Xb[1])[i / 2] = o;
        }
        {
            float4 a0 = ((const float4*)v)[i], a1 = ((const float4*)v)[i + 1];
            uint4 o = {pack_hf2(a0.x, a0.y), pack_hf2(a0.z, a0.w),
                       pack_hf2(a1.x, a1.y), pack_hf2(a1.z, a1.w)};
            ((uint4*)g_Xf)[i / 2] = o;
        }
        return;
    }
    // ---- bfold ---------------------------------------------------------------
    {
        int t = bid - 2816;
        const float* b1 = (t == 0) ? bq : (t == 1) ? bk : bv;
        const float* b2 = (t == 0) ? bqf : (t == 1) ? bkf : bvf;
        const float* Wf = (t == 0) ? Wqf : (t == 1) ? Wkf : Wvf;
#pragma unroll
        for (int kk = 0; kk < 4; kk++) {
            int n = tid + kk * 256;
            int h = n >> 6, o = n & 63;
            float s = b2[o];
            for (int i = 0; i < 64; i++) s += Wf[o * 64 + i] * b1[h * 64 + i];
            g_bc[t][n] = s;
        }
    }
}

// ---------------------------------------------------------------------------
// Projection GEMM v2: BM=256, BN=128 (2 heads), BK=32, 3-stage cp.async.
// 8 warps = 4m x 2n, warp tile 64x64 (acc 128 regs) -> 16 MACs per smem byte.
// grid flat 384: blocks [0,128) t=2 (V + fused V'), [128,256) Q, [256,384) K.
// smem: 3 stages x (256+128) x 40 u16 = 92160 B (1 CTA/SM).
// ---------------------------------------------------------------------------
#define BP 40
__global__ __launch_bounds__(256) void proj_all(const float* __restrict__ Wo) {
    extern __shared__ uint16_t sb[];

    int bid = blockIdx.x;
    const int t = (bid < 128) ? 2 : ((bid < 256) ? 0 : 1);
    const int r = (bid < 128) ? bid : ((bid < 256) ? bid - 128 : bid - 256);
    const int hp = r & 7;
    const int m0 = (r >> 3) * 256;

    const bool VM = (t == 2);
    const uint16_t* X = VM ? (const uint16_t*)g_Xf : (const uint16_t*)g_Xb[t];
    const uint16_t* W = VM ? (const uint16_t*)g_Wcf : (const uint16_t*)g_Wcb[t];
    const float* bias = g_bc[t];

    const int tid = threadIdx.x;
    const int w = tid >> 5, lane = tid & 31, g = lane >> 2, tg = lane & 3;
    const int wm = w & 3, wn = w >> 2;

    const int loA40 = ((lane & 7) + ((lane >> 3) & 1) * 8) * BP + ((lane >> 4) & 1) * 8;
    const int loB40 = ((lane & 7) + ((lane >> 4) & 1) * 8) * BP + ((lane >> 3) & 1) * 8;

    float acc[4][8][4] = {};

#define GLOAD(I, S)                                                                     \
    do {                                                                                \
        uint16_t* Xd = sb + (S) * 15360;                                                \
        uint16_t* Wd = Xd + 10240;                                                      \
        int k0_ = (I) * 32;                                                             \
        _Pragma("unroll")                                                               \
        for (int j = 0; j < 4; j++) {                                                   \
            int idx = tid + j * 256; int rr = idx >> 2, c = (idx & 3) * 8;              \
            cp16(Xd + rr * BP + c, X + (size_t)(m0 + rr) * Dd + k0_ + c);               \
        }                                                                               \
        _Pragma("unroll")                                                               \
        for (int j = 0; j < 2; j++) {                                                   \
            int idx = tid + j * 256; int rr = idx >> 2, c = (idx & 3) * 8;              \
            cp16(Wd + rr * BP + c, W + (size_t)(hp * 128 + rr) * Dd + k0_ + c);         \
        }                                                                               \
        asm volatile("cp.async.commit_group;");                                        \
    } while (0)

#define MAINLOOP(MMAOP)                                                                 \
    for (int i = 0; i < 32; i++) {                                                      \
        asm volatile("cp.async.wait_group 1;");                                         \
        __syncthreads();                                                                \
        if (i + 2 < 32) GLOAD(i + 2, (i + 2) % 3);                                      \
        else asm volatile("cp.async.commit_group;");                                    \
        const uint16_t* Xb_ = sb + (i % 3) * 15360;                                     \
        const uint16_t* Wb_ = Xb_ + 10240;                                              \
        _Pragma("unroll")                                                               \
        for (int ks = 0; ks < 2; ks++) {                                                \
            uint32_t a[4][4], b[4][4];                                                  \
            _Pragma("unroll")                                                           \
            for (int fm = 0; fm < 4; fm++)                                              \
                ldsm4(a[fm], Xb_ + (wm * 64 + fm * 16) * BP + ks * 16 + loA40);         \
            _Pragma("unroll")                                                           \
            for (int fnp = 0; fnp < 4; fnp++)                                           \
                ldsm4(b[fnp], Wb_ + (wn * 64 + fnp * 16) * BP + ks * 16 + loB40);       \
            _Pragma("unroll")                                                           \
            for (int fm = 0; fm < 4; fm++)                                              \
                _Pragma("unroll")                                                       \
                for (int fnp = 0; fnp < 4; fnp++) {                                     \
                    MMAOP(acc[fm][2 * fnp],     a[fm], b[fnp][0], b[fnp][1]);           \
                    MMAOP(acc[fm][2 * fnp + 1], a[fm], b[fnp][2], b[fnp][3]);           \
                }                                                                       \
        }                                                                               \
    }

    GLOAD(0, 0);
    GLOAD(1, 1);
    if (!VM) { MAINLOOP(mma16); }
    else     { MAINLOOP(mma16f); }
#undef MAINLOOP
#undef GLOAD

    const int b_ = m0 >> 10, s0 = m0 & 1023;  // m0 multiple of 256 -> single batch
    if (!VM) {
        __nv_bfloat16* Y = (t == 0) ? g_Qb : g_Kb;
        const float sc = (t == 0) ? QSCALE : 1.0f;
        const int head = hp * 2 + wn;
        const float* bh_ = bias + head * 64;
        uint16_t* dstb = (uint16_t*)Y + (((size_t)(b_ * Hh + head)) * Ss + s0) * DKk;
#pragma unroll
        for (int fm = 0; fm < 4; fm++) {
#pragma unroll
            for (int fn = 0; fn < 8; fn++) {
                int col = fn * 8 + 2 * tg;
                float b0 = bh_[col], b1 = bh_[col + 1];
                int lr0 = wm * 64 + fm * 16 + g, lr1 = lr0 + 8;
                *(uint32_t*)(dstb + (size_t)lr0 * DKk + col) =
                    pack_bf2(fmaxf(acc[fm][fn][0] + b0, 0.f) * sc,
                             fmaxf(acc[fm][fn][1] + b1, 0.f) * sc);
                *(uint32_t*)(dstb + (size_t)lr1 * DKk + col) =
                    pack_bf2(fmaxf(acc[fm][fn][2] + b0, 0.f) * sc,
                             fmaxf(acc[fm][fn][3] + b1, 0.f) * sc);
            }
        }
    } else {
        // ---- fused pass-2: V' = V @ Wo^T per head (fp16 mma) -----------------
        __syncthreads();
        uint16_t* Vt  = sb;                  // [256][136] fp16 (69632 B)
        uint16_t* WoS = sb + 256 * 136;      // [64][72]   fp16 ( 9216 B)

#pragma unroll
        for (int fm = 0; fm < 4; fm++) {
#pragma unroll
            for (int fn = 0; fn < 8; fn++) {
                int col = wn * 64 + fn * 8 + 2 * tg;
                float b0 = bias[hp * 128 + col], b1 = bias[hp * 128 + col + 1];
                int lr0 = wm * 64 + fm * 16 + g, lr1 = lr0 + 8;
                *(uint32_t*)(Vt + lr0 * 136 + col) = pack_hf2(fmaxf(acc[fm][fn][0] + b0, 0.f),
                                                              fmaxf(acc[fm][fn][1] + b1, 0.f));
                *(uint32_t*)(Vt + lr1 * 136 + col) = pack_hf2(fmaxf(acc[fm][fn][2] + b0, 0.f),
                                                              fmaxf(acc[fm][fn][3] + b1, 0.f));
            }
        }
#pragma unroll
        for (int j = 0; j < 4; j++) {
            int idx = tid + j * 256; int rr = idx >> 4, c = (idx & 15) * 4;
            float4 wv = *(const float4*)(Wo + rr * 64 + c);
            *(uint32_t*)(WoS + rr * 72 + c)     = pack_hf2(wv.x, wv.y);
            *(uint32_t*)(WoS + rr * 72 + c + 2) = pack_hf2(wv.z, wv.w);
        }
        __syncthreads();

        const int loA136 = ((lane & 7) + ((lane >> 3) & 1) * 8) * 136 + ((lane >> 4) & 1) * 8;
        const int loB72  = ((lane & 7) + ((lane >> 4) & 1) * 8) * 72 + ((lane >> 3) & 1) * 8;

#pragma unroll
        for (int j = 0; j < 2; j++) {
            const int head = hp * 2 + j, bh = b_ * Hh + head;
            float acc2[4][4][4] = {};
#pragma unroll
            for (int ks = 0; ks < 4; ks++) {
                uint32_t a[4][4], bfr[2][4];
#pragma unroll
                for (int fm = 0; fm < 4; fm++)
                    ldsm4(a[fm], Vt + (wm * 64 + fm * 16) * 136 + j * 64 + ks * 16 + loA136);
                ldsm4(bfr[0], WoS + (wn * 32) * 72 + ks * 16 + loB72);
                ldsm4(bfr[1], WoS + (wn * 32 + 16) * 72 + ks * 16 + loB72);
#pragma unroll
                for (int fm = 0; fm < 4; fm++) {
                    mma16f(acc2[fm][0], a[fm], bfr[0][0], bfr[0][1]);
                    mma16f(acc2[fm][1], a[fm], bfr[0][2], bfr[0][3]);
                    mma16f(acc2[fm][2], a[fm], bfr[1][0], bfr[1][1]);
                    mma16f(acc2[fm][3], a[fm], bfr[1][2], bfr[1][3]);
                }
            }
            uint16_t* dst = (uint16_t*)g_Vp + ((size_t)bh * Ss + s0) * DKk;
#pragma unroll
            for (int fm = 0; fm < 4; fm++) {
#pragma unroll
                for (int fn = 0; fn < 4; fn++) {
                    int col = wn * 32 + fn * 8 + 2 * tg;
                    int lr0 = wm * 64 + fm * 16 + g, lr1 = lr0 + 8;
                    *(uint32_t*)(dst + (size_t)lr0 * DKk + col) =
                        pack_hf2(acc2[fm][fn][0], acc2[fm][fn][1]);
                    *(uint32_t*)(dst + (size_t)lr1 * DKk + col) =
                        pack_hf2(acc2[fm][fn][2], acc2[fm][fn][3]);
                }
            }
        }
    }
}

// ---------------------------------------------------------------------------
// Flash attention v4 (unchanged, passing; ~92% of mma issue floor).
// ---------------------------------------------------------------------------
#define KP 72
__global__ __launch_bounds__(256, 2) void attn_tc(const int* __restrict__ mask,
                                                  const float* __restrict__ bo,
                                                  float* __restrict__ out) {
    extern __shared__ char smraw[];
    uint16_t* Kb = (uint16_t*)smraw;                   // [4][64][72]  36864 B
    uint16_t* Vb = (uint16_t*)(smraw + 36864);         // [4][64][72]  36864 B
    uint16_t* Qs = (uint16_t*)(smraw + 73728);         // [128][72]    18432 B
    int* ms = (int*)(smraw + 92160);                   // [4][64]       1024 B

    int bh = blockIdx.y, q0 = blockIdx.x * 128;
    const uint16_t* Qg = (const uint16_t*)g_Qb + ((size_t)bh * Ss + q0) * DKk;
    const uint16_t* Kg = (const uint16_t*)g_Kb + (size_t)bh * Ss * DKk;
    const uint16_t* Vg = (const uint16_t*)g_Vp + (size_t)bh * Ss * DKk;

    int tid = threadIdx.x, w = tid >> 5, lane = tid & 31, g = lane >> 2, tg = lane & 3;
    const int loA72 = ((lane & 7) + ((lane >> 3) & 1) * 8) * KP + ((lane >> 4) & 1) * 8;
    const int loB72 = ((lane & 7) + ((lane >> 4) & 1) * 8) * KP + ((lane >> 3) & 1) * 8;
    const int loBT72 = ((lane & 7) + ((lane >> 3) & 1) * 8) * KP + ((lane >> 4) & 1) * 8;

#pragma unroll
    for (int j = 0; j < 4; j++) {
        int idx = tid + j * 256; int r = idx >> 3, c = (idx & 7) * 8;
        *(uint4*)(Qs + r * KP + c) = *(const uint4*)(Qg + (size_t)r * DKk + c);
    }
    __syncthreads();
    uint32_t qa[4][4];
#pragma unroll
    for (int ks = 0; ks < 4; ks++)
        ldsm4(qa[ks], Qs + w * 16 * KP + ks * 16 + loA72);

#define AFILL(KT, BUF)                                                                  \
    do {                                                                                \
        const uint16_t* kg = Kg + (size_t)(KT) * 64 * DKk;                              \
        const uint16_t* vg = Vg + (size_t)(KT) * 64 * DKk;                              \
        _Pragma("unroll")                                                               \
        for (int j = 0; j < 2; j++) {                                                   \
            int idx = tid + j * 256; int r = idx >> 3, c = (idx & 7) * 8;               \
            cp16(Kb + ((BUF) * 64 + r) * KP + c, kg + (size_t)r * DKk + c);             \
            cp16(Vb + ((BUF) * 64 + r) * KP + c, vg + (size_t)r * DKk + c);             \
        }                                                                               \
        if (tid < 16)                                                                   \
            cp16(ms + (BUF) * 64 + tid * 4, mask + (size_t)bh * Ss + (KT) * 64 + tid * 4); \
        asm volatile("cp.async.commit_group;");                                        \
    } while (0)

    float oacc[8][4] = {};
    float sumA = 0.f, sumB = 0.f;

    AFILL(0, 0);
    AFILL(1, 1);
    AFILL(2, 2);
    for (int kt = 0; kt < 16; kt++) {
        int buf = kt & 3;
        asm volatile("cp.async.wait_group 2;");
        __syncthreads();
        if (kt + 3 < 16) AFILL(kt + 3, (kt + 3) & 3);
        else asm volatile("cp.async.commit_group;");

        const uint16_t* Kt = Kb + buf * 64 * KP;
        const uint16_t* Vt = Vb + buf * 64 * KP;
        const int* mt = ms + buf * 64;

        float sacc[8][4] = {};
#pragma unroll
        for (int ks = 0; ks < 4; ks++) {
#pragma unroll
            for (int fnp = 0; fnp < 4; fnp++) {
                uint32_t b[4];
                ldsm4(b, Kt + fnp * 16 * KP + ks * 16 + loB72);
                mma16(sacc[2 * fnp],     qa[ks], b[0], b[1]);
                mma16(sacc[2 * fnp + 1], qa[ks], b[2], b[3]);
            }
        }
#pragma unroll
        for (int fn = 0; fn < 8; fn++) {
            int c0 = fn * 8 + 2 * tg;
            bool k0m = (mt[c0] == 0), k1m = (mt[c0 + 1] == 0);
            sacc[fn][0] = k0m ? 0.f : ex2f(sacc[fn][0]);
            sacc[fn][1] = k1m ? 0.f : ex2f(sacc[fn][1]);
            sacc[fn][2] = k0m ? 0.f : ex2f(sacc[fn][2]);
            sacc[fn][3] = k1m ? 0.f : ex2f(sacc[fn][3]);
            sumA += sacc[fn][0] + sacc[fn][1];
            sumB += sacc[fn][2] + sacc[fn][3];
        }
#pragma unroll
        for (int ks = 0; ks < 4; ks++) {
            uint32_t pa[4];
            pa[0] = pack_hf2(sacc[2 * ks][0],     sacc[2 * ks][1]);
            pa[1] = pack_hf2(sacc[2 * ks][2],     sacc[2 * ks][3]);
            pa[2] = pack_hf2(sacc[2 * ks + 1][0], sacc[2 * ks + 1][1]);
            pa[3] = pack_hf2(sacc[2 * ks + 1][2], sacc[2 * ks + 1][3]);
#pragma unroll
            for (int fnp = 0; fnp < 4; fnp++) {
                uint32_t b[4];
                ldsm4t(b, Vt + (ks * 16) * KP + fnp * 16 + loBT72);
                mma16f(oacc[2 * fnp],     pa, b[0], b[1]);
                mma16f(oacc[2 * fnp + 1], pa, b[2], b[3]);
            }
        }
    }
#undef AFILL

    sumA += __shfl_xor_sync(~0u, sumA, 1); sumA += __shfl_xor_sync(~0u, sumA, 2);
    sumB += __shfl_xor_sync(~0u, sumB, 1); sumB += __shfl_xor_sync(~0u, sumB, 2);
    float invA = 1.f / sumA, invB = 1.f / sumB;
    int b_ = bh >> 4, h = bh & 15;
#pragma unroll
    for (int fn = 0; fn < 8; fn++) {
        int col = fn * 8 + 2 * tg;
        float b0v = bo[col], b1v = bo[col + 1];
        int r0 = q0 + w * 16 + g, r1 = r0 + 8;
        *(float2*)(out + ((size_t)(b_ * Ss + r0)) * Dd + h * 64 + col) =
            make_float2(oacc[fn][0] * invA + b0v, oacc[fn][1] * invA + b1v);
        *(float2*)(out + ((size_t)(b_ * Ss + r1)) * Dd + h * 64 + col) =
            make_float2(oacc[fn][2] * invB + b0v, oacc[fn][3] * invB + b1v);
    }
}

// ---------------------------------------------------------------------------
extern "C" void kernel_launch(void* const* d_in, const int* in_sizes, int n_in,
                              void* d_out, int out_size) {
    const float* q   = (const float*)d_in[0];
    const float* k   = (const float*)d_in[1];
    const float* v   = (const float*)d_in[2];
    const int*   msk = (const int*)d_in[3];
    const float* Wq  = (const float*)d_in[4];
    const float* bq  = (const float*)d_in[5];
    const float* Wk  = (const float*)d_in[6];
    const float* bk  = (const float*)d_in[7];
    const float* Wv  = (const float*)d_in[8];
    const float* bv  = (const float*)d_in[9];
    const float* Wqf = (const float*)d_in[10];
    const float* bqf = (const float*)d_in[11];
    const float* Wkf = (const float*)d_in[12];
    const float* bkf = (const float*)d_in[13];
    const float* Wvf = (const float*)d_in[14];
    const float* bvf = (const float*)d_in[15];
    const float* Wo  = (const float*)d_in[16];
    const float* bo  = (const float*)d_in[17];
    float* out = (float*)d_out;

    const int proj_smem = 3 * (256 + 128) * BP * 2;  // 92160
    const int attn_smem = 93184;

    static int cfg = 0;
    if (!cfg) {
        cudaFuncSetAttribute(proj_all, cudaFuncAttributeMaxDynamicSharedMemorySize, proj_smem);
        cudaFuncSetAttribute(attn_tc, cudaFuncAttributeMaxDynamicSharedMemorySize, attn_smem);
        cfg = 1;
    }

    prologue<<<2819, 256>>>(q, k, v, Wq, Wqf, Wk, Wkf, Wv, Wvf,
                            bq, bqf, bk, bkf, bv, bvf);
    proj_all<<<384, 256, proj_smem>>>(Wo);
    attn_tc<<<dim3(8, 64), 256, attn_smem>>>(msk, bo, out);
}

// round 15
// speedup vs baseline: 1.0797x; 1.0797x over previous
#include <cuda_runtime.h>
#include <cuda_bf16.h>
#include <cuda_fp16.h>
#include <math.h>
#include <stdint.h>

#define Bb 4
#define Ss 1024
#define Dd 1024
#define Hh 16
#define DKk 64

#define QSCALE 0.18033688011112042f
#define MASKVAL -14426.950408889634f

// ---------------------------------------------------------------------------
// Device scratch
// ---------------------------------------------------------------------------
__device__ __nv_bfloat16 g_Xb[2][4096 * 1024];   // bf16 q,k inputs
__device__ __half        g_Xf[4096 * 1024];      // fp16 v input
__device__ __nv_bfloat16 g_Wcb[2][1024 * 1024];  // folded Wq,Wk (bf16)
__device__ __half        g_Wcf[1024 * 1024];     // folded Wv (fp16)
__device__ float         g_bc[3][1024];          // folded biases
__device__ __nv_bfloat16 g_Qb[64 * 1024 * 64];   // per-head Q (bf16, pre-scaled)
__device__ __nv_bfloat16 g_Kb[64 * 1024 * 64];   // per-head K (bf16)
__device__ __half        g_Vp[64 * 1024 * 64];   // V' = V @ Wo^T (fp16) [bh][s][d]

// ---------------------------------------------------------------------------
// helpers
// ---------------------------------------------------------------------------
__device__ __forceinline__ void mma16(float (&d)[4], const uint32_t (&a)[4],
                                      uint32_t b0, uint32_t b1) {
    asm volatile(
        "mma.sync.aligned.m16n8k16.row.col.f32.bf16.bf16.f32 "
        "{%0,%1,%2,%3},{%4,%5,%6,%7},{%8,%9},{%0,%1,%2,%3};"
        : "+f"(d[0]), "+f"(d[1]), "+f"(d[2]), "+f"(d[3])
        : "r"(a[0]), "r"(a[1]), "r"(a[2]), "r"(a[3]), "r"(b0), "r"(b1));
}
__device__ __forceinline__ void mma16f(float (&d)[4], const uint32_t (&a)[4],
                                       uint32_t b0, uint32_t b1) {
    asm volatile(
        "mma.sync.aligned.m16n8k16.row.col.f32.f16.f16.f32 "
        "{%0,%1,%2,%3},{%4,%5,%6,%7},{%8,%9},{%0,%1,%2,%3};"
        : "+f"(d[0]), "+f"(d[1]), "+f"(d[2]), "+f"(d[3])
        : "r"(a[0]), "r"(a[1]), "r"(a[2]), "r"(a[3]), "r"(b0), "r"(b1));
}
__device__ __forceinline__ void ldsm4(uint32_t (&r)[4], const uint16_t* p) {
    uint32_t a = (uint32_t)__cvta_generic_to_shared(p);
    asm volatile("ldmatrix.sync.aligned.m8n8.x4.shared.b16 {%0,%1,%2,%3},[%4];"
                 : "=r"(r[0]), "=r"(r[1]), "=r"(r[2]), "=r"(r[3]) : "r"(a));
}
__device__ __forceinline__ void ldsm4t(uint32_t (&r)[4], const uint16_t* p) {
    uint32_t a = (uint32_t)__cvta_generic_to_shared(p);
    asm volatile("ldmatrix.sync.aligned.m8n8.x4.trans.shared.b16 {%0,%1,%2,%3},[%4];"
                 : "=r"(r[0]), "=r"(r[1]), "=r"(r[2]), "=r"(r[3]) : "r"(a));
}
__device__ __forceinline__ void cp16(void* s, const void* g) {
    uint32_t sa = (uint32_t)__cvta_generic_to_shared(s);
    asm volatile("cp.async.cg.shared.global [%0], [%1], 16;" :: "r"(sa), "l"(g));
}
__device__ __forceinline__ uint32_t pack_bf2(float a, float b) {
    __nv_bfloat162 t = __float22bfloat162_rn(make_float2(a, b));
    return *reinterpret_cast<uint32_t*>(&t);
}
__device__ __forceinline__ uint32_t pack_hf2(float a, float b) {
    __half2 t = __floats2half2_rn(a, b);
    return *reinterpret_cast<uint32_t*>(&t);
}
__device__ __forceinline__ float ex2f(float x) {
    float y; asm("ex2.approx.f32 %0,%1;" : "=f"(y) : "f"(x)); return y;
}

// ---------------------------------------------------------------------------
// Merged prologue (round-14 version: vectorized fold LDS, fold-first):
//   blocks [0, 768)     : fold
//   blocks [768, 2816)  : preround
//   blocks [2816, 2819) : bfold
// ---------------------------------------------------------------------------
__global__ __launch_bounds__(256) void prologue(
    const float* __restrict__ q, const float* __restrict__ k, const float* __restrict__ v,
    const float* __restrict__ Wq, const float* __restrict__ Wqf,
    const float* __restrict__ Wk, const float* __restrict__ Wkf,
    const float* __restrict__ Wv, const float* __restrict__ Wvf,
    const float* __restrict__ bq, const float* __restrict__ bqf,
    const float* __restrict__ bk, const float* __restrict__ bkf,
    const float* __restrict__ bv, const float* __restrict__ bvf) {
    int bid = blockIdx.x;
    int tid = threadIdx.x;

    if (bid < 768) {
        // ---- fold: Wc[(h*64+o)*1024+j] = sum_i Wf[o,i] * Wbig[h*64+i, j] -----
        int t = bid >> 8, h = (bid >> 4) & 15, j0 = (bid & 15) * 64;
        const float* Wbig = (t == 0) ? Wq : (t == 1) ? Wk : Wv;
        const float* Wf   = (t == 0) ? Wqf : (t == 1) ? Wkf : Wvf;

        __shared__ float fsT[64][68];  // Wf transposed: fsT[i][o]
        __shared__ float bs[64][68];   // Wbig rows (16B-aligned rows)

        for (int idx = tid; idx < 64 * 16; idx += 256) {
            int r = idx >> 4, c4 = (idx & 15) * 4;
            float4 fv = *(const float4*)(Wf + r * 64 + c4);
            fsT[c4][r] = fv.x; fsT[c4 + 1][r] = fv.y;
            fsT[c4 + 2][r] = fv.z; fsT[c4 + 3][r] = fv.w;
            float4 bv2 = *(const float4*)(Wbig + (h * 64 + r) * Dd + j0 + c4);
            *(float4*)&bs[r][c4] = bv2;
        }
        __syncthreads();

        int ty = tid >> 4, tx = tid & 15;
        float acc[4][4] = {};
#pragma unroll 8
        for (int i = 0; i < 64; i++) {
            float4 av = *(const float4*)&fsT[i][ty * 4];
            float4 bv2 = *(const float4*)&bs[i][tx * 4];
            float a[4] = {av.x, av.y, av.z, av.w};
            float b[4] = {bv2.x, bv2.y, bv2.z, bv2.w};
#pragma unroll
            for (int u = 0; u < 4; u++)
#pragma unroll
                for (int w = 0; w < 4; w++) acc[u][w] += a[u] * b[w];
        }
        if (t < 2) {
            uint32_t* dst = (uint32_t*)g_Wcb[t];
#pragma unroll
            for (int u = 0; u < 4; u++) {
                size_t row = (size_t)(h * 64 + ty * 4 + u) * Dd + j0 + tx * 4;
                dst[row / 2]     = pack_bf2(acc[u][0], acc[u][1]);
                dst[row / 2 + 1] = pack_bf2(acc[u][2], acc[u][3]);
            }
        } else {
            uint32_t* dst = (uint32_t*)g_Wcf;
#pragma unroll
            for (int u = 0; u < 4; u++) {
                size_t row = (size_t)(h * 64 + ty * 4 + u) * Dd + j0 + tx * 4;
                dst[row / 2]     = pack_hf2(acc[u][0], acc[u][1]);
                dst[row / 2 + 1] = pack_hf2(acc[u][2], acc[u][3]);
            }
        }
        return;
    }
    if (bid < 2816) {
        // ---- preround: 2 consecutive float4 per tensor per thread ------------
        size_t i = ((size_t)(bid - 768) * 256 + tid) * 2;
        {
            float4 a0 = ((const float4*)q)[i], a1 = ((const float4*)q)[i + 1];
            uint4 o = {pack_bf2(a0.x, a0.y), pack_bf2(a0.z, a0.w),
                       pack_bf2(a1.x, a1.y), pack_bf2(a1.z, a1.w)};
            ((uint4*)g_Xb[0])[i / 2] = o;
        }
        {
            float4 a0 = ((const float4*)k)[i], a1 = ((const float4*)k)[i + 1];
            uint4 o = {pack_bf2(a0.x, a0.y), pack_bf2(a0.z, a0.w),
                       pack_bf2(a1.x, a1.y), pack_bf2(a1.z, a1.w)};
            ((uint4*)g_Xb[1])[i / 2] = o;
        }
        {
            float4 a0 = ((const float4*)v)[i], a1 = ((const float4*)v)[i + 1];
            uint4 o = {pack_hf2(a0.x, a0.y), pack_hf2(a0.z, a0.w),
                       pack_hf2(a1.x, a1.y), pack_hf2(a1.z, a1.w)};
            ((uint4*)g_Xf)[i / 2] = o;
        }
        return;
    }
    // ---- bfold ---------------------------------------------------------------
    {
        int t = bid - 2816;
        const float* b1 = (t == 0) ? bq : (t == 1) ? bk : bv;
        const float* b2 = (t == 0) ? bqf : (t == 1) ? bkf : bvf;
        const float* Wf = (t == 0) ? Wqf : (t == 1) ? Wkf : Wvf;
#pragma unroll
        for (int kk = 0; kk < 4; kk++) {
            int n = tid + kk * 256;
            int h = n >> 6, o = n & 63;
            float s = b2[o];
            for (int i = 0; i < 64; i++) s += Wf[o * 64 + i] * b1[h * 64 + i];
            g_bc[t][n] = s;
        }
    }
}

// ---------------------------------------------------------------------------
// Unified projection GEMM (round-13 version, verified 98us @ 2 CTAs/SM).
// BM=128, BN=128 (2 heads), BK=32, 3-stage. Flat grid, V-tensor CTAs FIRST:
//   blocks [0, 256)   : t=2 (V + fused V' pass-2, longest CTAs)
//   blocks [256, 512) : t=0 (Q)
//   blocks [512, 768) : t=1 (K)
// ---------------------------------------------------------------------------
#define BP 40
__global__ __launch_bounds__(256, 2) void proj_all(const float* __restrict__ Wo) {
    extern __shared__ uint16_t sb[];

    int bid = blockIdx.x;
    const int t = (bid < 256) ? 2 : ((bid < 512) ? 0 : 1);
    const int r = (bid < 256) ? bid : ((bid < 512) ? bid - 256 : bid - 512);
    const int hp = r & 7;
    const int m0 = (r >> 3) * 128;

    const bool VM = (t == 2);
    const uint16_t* X = VM ? (const uint16_t*)g_Xf : (const uint16_t*)g_Xb[t];
    const uint16_t* W = VM ? (const uint16_t*)g_Wcf : (const uint16_t*)g_Wcb[t];
    const float* bias = g_bc[t];

    const int tid = threadIdx.x;
    const int w = tid >> 5, lane = tid & 31, g = lane >> 2, tg = lane & 3;
    const int wm = w & 3, wn = w >> 2;

    const int loA40 = ((lane & 7) + ((lane >> 3) & 1) * 8) * BP + ((lane >> 4) & 1) * 8;
    const int loB40 = ((lane & 7) + ((lane >> 4) & 1) * 8) * BP + ((lane >> 3) & 1) * 8;

    float acc[2][8][4] = {};

#define GLOAD(I, S)                                                                     \
    do {                                                                                \
        uint16_t* Xd = sb + (S) * 10240;                                                \
        uint16_t* Wd = Xd + 5120;                                                       \
        int k0_ = (I) * 32;                                                             \
        _Pragma("unroll")                                                               \
        for (int j = 0; j < 2; j++) {                                                   \
            int idx = tid + j * 256; int rr = idx >> 2, c = (idx & 3) * 8;              \
            cp16(Xd + rr * BP + c, X + (size_t)(m0 + rr) * Dd + k0_ + c);               \
        }                                                                               \
        _Pragma("unroll")                                                               \
        for (int j = 0; j < 2; j++) {                                                   \
            int idx = tid + j * 256; int rr = idx >> 2, c = (idx & 3) * 8;              \
            cp16(Wd + rr * BP + c, W + (size_t)(hp * 128 + rr) * Dd + k0_ + c);         \
        }                                                                               \
        asm volatile("cp.async.commit_group;");                                        \
    } while (0)

#define MAINLOOP(MMAOP)                                                                 \
    for (int i = 0; i < 32; i++) {                                                      \
        asm volatile("cp.async.wait_group 1;");                                         \
        __syncthreads();                                                                \
        if (i + 2 < 32) GLOAD(i + 2, (i + 2) % 3);                                      \
        else asm volatile("cp.async.commit_group;");                                    \
        const uint16_t* Xb_ = sb + (i % 3) * 10240;                                     \
        const uint16_t* Wb_ = Xb_ + 5120;                                               \
        _Pragma("unroll")                                                               \
        for (int ks = 0; ks < 2; ks++) {                                                \
            uint32_t a[2][4], b[4][4];                                                  \
            ldsm4(a[0], Xb_ + (wm * 32) * BP + ks * 16 + loA40);                        \
            ldsm4(a[1], Xb_ + (wm * 32 + 16) * BP + ks * 16 + loA40);                   \
            _Pragma("unroll")                                                           \
            for (int fnp = 0; fnp < 4; fnp++)                                           \
                ldsm4(b[fnp], Wb_ + (wn * 64 + fnp * 16) * BP + ks * 16 + loB40);       \
            _Pragma("unroll")                                                           \
            for (int fm = 0; fm < 2; fm++)                                              \
                _Pragma("unroll")                                                       \
                for (int fnp = 0; fnp < 4; fnp++) {                                     \
                    MMAOP(acc[fm][2 * fnp],     a[fm], b[fnp][0], b[fnp][1]);           \
                    MMAOP(acc[fm][2 * fnp + 1], a[fm], b[fnp][2], b[fnp][3]);           \
                }                                                                       \
        }                                                                               \
    }

    GLOAD(0, 0);
    GLOAD(1, 1);
    if (!VM) { MAINLOOP(mma16); }
    else     { MAINLOOP(mma16f); }
#undef MAINLOOP
#undef GLOAD

    const int b_ = m0 >> 10, s0 = m0 & 1023;
    if (!VM) {
        __nv_bfloat16* Y = (t == 0) ? g_Qb : g_Kb;
        const float sc = (t == 0) ? QSCALE : 1.0f;
        const int head = hp * 2 + wn;
        const float* bh_ = bias + head * 64;
#pragma unroll
        for (int fm = 0; fm < 2; fm++) {
#pragma unroll
            for (int fn = 0; fn < 8; fn++) {
                int col = fn * 8 + 2 * tg;
                float b0 = bh_[col], b1 = bh_[col + 1];
                int r0 = m0 + wm * 32 + fm * 16 + g, r1 = r0 + 8;
                uint32_t v0 = pack_bf2(fmaxf(acc[fm][fn][0] + b0, 0.f) * sc,
                                       fmaxf(acc[fm][fn][1] + b1, 0.f) * sc);
                uint32_t v1 = pack_bf2(fmaxf(acc[fm][fn][2] + b0, 0.f) * sc,
                                       fmaxf(acc[fm][fn][3] + b1, 0.f) * sc);
                {
                    int bb = r0 >> 10, s = r0 & 1023;
                    *(uint32_t*)((uint16_t*)Y + (((size_t)(bb * Hh + head)) * Ss + s) * DKk + col) = v0;
                }
                {
                    int bb = r1 >> 10, s = r1 & 1023;
                    *(uint32_t*)((uint16_t*)Y + (((size_t)(bb * Hh + head)) * Ss + s) * DKk + col) = v1;
                }
            }
        }
    } else {
        // ---- fused pass-2: V' = V @ Wo^T per head (fp16 mma) -----------------
        __syncthreads();
        uint16_t* Vt  = sb;                  // [128][136] fp16 (34816 B)
        uint16_t* WoS = sb + 128 * 136;      // [64][72]   fp16 ( 9216 B)

#pragma unroll
        for (int fm = 0; fm < 2; fm++) {
#pragma unroll
            for (int fn = 0; fn < 8; fn++) {
                int col = wn * 64 + fn * 8 + 2 * tg;
                float b0 = bias[hp * 128 + col], b1 = bias[hp * 128 + col + 1];
                int lr0 = wm * 32 + fm * 16 + g, lr1 = lr0 + 8;
                *(uint32_t*)(Vt + lr0 * 136 + col) = pack_hf2(fmaxf(acc[fm][fn][0] + b0, 0.f),
                                                              fmaxf(acc[fm][fn][1] + b1, 0.f));
                *(uint32_t*)(Vt + lr1 * 136 + col) = pack_hf2(fmaxf(acc[fm][fn][2] + b0, 0.f),
                                                              fmaxf(acc[fm][fn][3] + b1, 0.f));
            }
        }
#pragma unroll
        for (int j = 0; j < 4; j++) {
            int idx = tid + j * 256; int rr = idx >> 4, c = (idx & 15) * 4;
            float4 wv = *(const float4*)(Wo + rr * 64 + c);
            *(uint32_t*)(WoS + rr * 72 + c)     = pack_hf2(wv.x, wv.y);
            *(uint32_t*)(WoS + rr * 72 + c + 2) = pack_hf2(wv.z, wv.w);
        }
        __syncthreads();

        const int loA136 = ((lane & 7) + ((lane >> 3) & 1) * 8) * 136 + ((lane >> 4) & 1) * 8;
        const int loB72  = ((lane & 7) + ((lane >> 4) & 1) * 8) * 72 + ((lane >> 3) & 1) * 8;

#pragma unroll
        for (int j = 0; j < 2; j++) {
            const int head = hp * 2 + j, bh = b_ * Hh + head;
            float acc2[2][4][4] = {};
#pragma unroll
            for (int ks = 0; ks < 4; ks++) {
                uint32_t a[2][4], bfr[2][4];
                ldsm4(a[0], Vt + (wm * 32) * 136 + j * 64 + ks * 16 + loA136);
                ldsm4(a[1], Vt + (wm * 32 + 16) * 136 + j * 64 + ks * 16 + loA136);
                ldsm4(bfr[0], WoS + (wn * 32) * 72 + ks * 16 + loB72);
                ldsm4(bfr[1], WoS + (wn * 32 + 16) * 72 + ks * 16 + loB72);
#pragma unroll
                for (int fm = 0; fm < 2; fm++) {
                    mma16f(acc2[fm][0], a[fm], bfr[0][0], bfr[0][1]);
                    mma16f(acc2[fm][1], a[fm], bfr[0][2], bfr[0][3]);
                    mma16f(acc2[fm][2], a[fm], bfr[1][0], bfr[1][1]);
                    mma16f(acc2[fm][3], a[fm], bfr[1][2], bfr[1][3]);
                }
            }
            uint16_t* dst = (uint16_t*)g_Vp + ((size_t)bh * Ss + s0) * DKk;
#pragma unroll
            for (int fm = 0; fm < 2; fm++) {
#pragma unroll
                for (int fn = 0; fn < 4; fn++) {
                    int col = wn * 32 + fn * 8 + 2 * tg;
                    int lr0 = wm * 32 + fm * 16 + g, lr1 = lr0 + 8;
                    *(uint32_t*)(dst + (size_t)lr0 * DKk + col) =
                        pack_hf2(acc2[fm][fn][0], acc2[fm][fn][1]);
                    *(uint32_t*)(dst + (size_t)lr1 * DKk + col) =
                        pack_hf2(acc2[fm][fn][2], acc2[fm][fn][3]);
                }
            }
        }
    }
}

// ---------------------------------------------------------------------------
// Flash attention v4 (unchanged, passing; ~92% of mma issue floor).
// ---------------------------------------------------------------------------
#define KP 72
__global__ __launch_bounds__(256, 2) void attn_tc(const int* __restrict__ mask,
                                                  const float* __restrict__ bo,
                                                  float* __restrict__ out) {
    extern __shared__ char smraw[];
    uint16_t* Kb = (uint16_t*)smraw;                   // [4][64][72]  36864 B
    uint16_t* Vb = (uint16_t*)(smraw + 36864);         // [4][64][72]  36864 B
    uint16_t* Qs = (uint16_t*)(smraw + 73728);         // [128][72]    18432 B
    int* ms = (int*)(smraw + 92160);                   // [4][64]       1024 B

    int bh = blockIdx.y, q0 = blockIdx.x * 128;
    const uint16_t* Qg = (const uint16_t*)g_Qb + ((size_t)bh * Ss + q0) * DKk;
    const uint16_t* Kg = (const uint16_t*)g_Kb + (size_t)bh * Ss * DKk;
    const uint16_t* Vg = (const uint16_t*)g_Vp + (size_t)bh * Ss * DKk;

    int tid = threadIdx.x, w = tid >> 5, lane = tid & 31, g = lane >> 2, tg = lane & 3;
    const int loA72 = ((lane & 7) + ((lane >> 3) & 1) * 8) * KP + ((lane >> 4) & 1) * 8;
    const int loB72 = ((lane & 7) + ((lane >> 4) & 1) * 8) * KP + ((lane >> 3) & 1) * 8;
    const int loBT72 = ((lane & 7) + ((lane >> 3) & 1) * 8) * KP + ((lane >> 4) & 1) * 8;

#pragma unroll
    for (int j = 0; j < 4; j++) {
        int idx = tid + j * 256; int r = idx >> 3, c = (idx & 7) * 8;
        *(uint4*)(Qs + r * KP + c) = *(const uint4*)(Qg + (size_t)r * DKk + c);
    }
    __syncthreads();
    uint32_t qa[4][4];
#pragma unroll
    for (int ks = 0; ks < 4; ks++)
        ldsm4(qa[ks], Qs + w * 16 * KP + ks * 16 + loA72);

#define AFILL(KT, BUF)                                                                  \
    do {                                                                                \
        const uint16_t* kg = Kg + (size_t)(KT) * 64 * DKk;                              \
        const uint16_t* vg = Vg + (size_t)(KT) * 64 * DKk;                              \
        _Pragma("unroll")                                                               \
        for (int j = 0; j < 2; j++) {                                                   \
            int idx = tid + j * 256; int r = idx >> 3, c = (idx & 7) * 8;               \
            cp16(Kb + ((BUF) * 64 + r) * KP + c, kg + (size_t)r * DKk + c);             \
            cp16(Vb + ((BUF) * 64 + r) * KP + c, vg + (size_t)r * DKk + c);             \
        }                                                                               \
        if (tid < 16)                                                                   \
            cp16(ms + (BUF) * 64 + tid * 4, mask + (size_t)bh * Ss + (KT) * 64 + tid * 4); \
        asm volatile("cp.async.commit_group;");                                        \
    } while (0)

    float oacc[8][4] = {};
    float sumA = 0.f, sumB = 0.f;

    AFILL(0, 0);
    AFILL(1, 1);
    AFILL(2, 2);
    for (int kt = 0; kt < 16; kt++) {
        int buf = kt & 3;
        asm volatile("cp.async.wait_group 2;");
        __syncthreads();
        if (kt + 3 < 16) AFILL(kt + 3, (kt + 3) & 3);
        else asm volatile("cp.async.commit_group;");

        const uint16_t* Kt = Kb + buf * 64 * KP;
        const uint16_t* Vt = Vb + buf * 64 * KP;
        const int* mt = ms + buf * 64;

        float sacc[8][4] = {};
#pragma unroll
        for (int ks = 0; ks < 4; ks++) {
#pragma unroll
            for (int fnp = 0; fnp < 4; fnp++) {
                uint32_t b[4];
                ldsm4(b, Kt + fnp * 16 * KP + ks * 16 + loB72);
                mma16(sacc[2 * fnp],     qa[ks], b[0], b[1]);
                mma16(sacc[2 * fnp + 1], qa[ks], b[2], b[3]);
            }
        }
#pragma unroll
        for (int fn = 0; fn < 8; fn++) {
            int c0 = fn * 8 + 2 * tg;
            bool k0m = (mt[c0] == 0), k1m = (mt[c0 + 1] == 0);
            sacc[fn][0] = k0m ? 0.f : ex2f(sacc[fn][0]);
            sacc[fn][1] = k1m ? 0.f : ex2f(sacc[fn][1]);
            sacc[fn][2] = k0m ? 0.f : ex2f(sacc[fn][2]);
            sacc[fn][3] = k1m ? 0.f : ex2f(sacc[fn][3]);
            sumA += sacc[fn][0] + sacc[fn][1];
            sumB += sacc[fn][2] + sacc[fn][3];
        }
#pragma unroll
        for (int ks = 0; ks < 4; ks++) {
            uint32_t pa[4];
            pa[0] = pack_hf2(sacc[2 * ks][0],     sacc[2 * ks][1]);
            pa[1] = pack_hf2(sacc[2 * ks][2],     sacc[2 * ks][3]);
            pa[2] = pack_hf2(sacc[2 * ks + 1][0], sacc[2 * ks + 1][1]);
            pa[3] = pack_hf2(sacc[2 * ks + 1][2], sacc[2 * ks + 1][3]);
#pragma unroll
            for (int fnp = 0; fnp < 4; fnp++) {
                uint32_t b[4];
                ldsm4t(b, Vt + (ks * 16) * KP + fnp * 16 + loBT72);
                mma16f(oacc[2 * fnp],     pa, b[0], b[1]);
                mma16f(oacc[2 * fnp + 1], pa, b[2], b[3]);
            }
        }
    }
#undef AFILL

    sumA += __shfl_xor_sync(~0u, sumA, 1); sumA += __shfl_xor_sync(~0u, sumA, 2);
    sumB += __shfl_xor_sync(~0u, sumB, 1); sumB += __shfl_xor_sync(~0u, sumB, 2);
    float invA = 1.f / sumA, invB = 1.f / sumB;
    int b_ = bh >> 4, h = bh & 15;
#pragma unroll
    for (int fn = 0; fn < 8; fn++) {
        int col = fn * 8 + 2 * tg;
        float b0v = bo[col], b1v = bo[col + 1];
        int r0 = q0 + w * 16 + g, r1 = r0 + 8;
        *(float2*)(out + ((size_t)(b_ * Ss + r0)) * Dd + h * 64 + col) =
            make_float2(oacc[fn][0] * invA + b0v, oacc[fn][1] * invA + b1v);
        *(float2*)(out + ((size_t)(b_ * Ss + r1)) * Dd + h * 64 + col) =
            make_float2(oacc[fn][2] * invB + b0v, oacc[fn][3] * invB + b1v);
    }
}

// ---------------------------------------------------------------------------
extern "C" void kernel_launch(void* const* d_in, const int* in_sizes, int n_in,
                              void* d_out, int out_size) {
    const float* q   = (const float*)d_in[0];
    const float* k   = (const float*)d_in[1];
    const float* v   = (const float*)d_in[2];
    const int*   msk = (const int*)d_in[3];
    const float* Wq  = (const float*)d_in[4];
    const float* bq  = (const float*)d_in[5];
    const float* Wk  = (const float*)d_in[6];
    const float* bk  = (const float*)d_in[7];
    const float* Wv  = (const float*)d_in[8];
    const float* bv  = (const float*)d_in[9];
    const float* Wqf = (const float*)d_in[10];
    const float* bqf = (const float*)d_in[11];
    const float* Wkf = (const float*)d_in[12];
    const float* bkf = (const float*)d_in[13];
    const float* Wvf = (const float*)d_in[14];
    const float* bvf = (const float*)d_in[15];
    const float* Wo  = (const float*)d_in[16];
    const float* bo  = (const float*)d_in[17];
    float* out = (float*)d_out;

    const int proj_smem = 3 * 2 * 128 * BP * 2;  // 61440
    const int attn_smem = 93184;

    static int cfg = 0;
    if (!cfg) {
        cudaFuncSetAttribute(proj_all, cudaFuncAttributeMaxDynamicSharedMemorySize, proj_smem);
        cudaFuncSetAttribute(attn_tc, cudaFuncAttributeMaxDynamicSharedMemorySize, attn_smem);
        cfg = 1;
    }

    prologue<<<2819, 256>>>(q, k, v, Wq, Wqf, Wk, Wkf, Wv, Wvf,
                            bq, bqf, bk, bkf, bv, bvf);
    proj_all<<<768, 256, proj_smem>>>(Wo);
    attn_tc<<<dim3(8, 64), 256, attn_smem>>>(msk, bo, out);
}